// round 15
// baseline (speedup 1.0000x reference)
#include <cuda_runtime.h>
#include <cuda_bf16.h>
#include <math.h>
#include <stdint.h>

// ---------------- static scratch (no allocations allowed) ----------------
#define MAXN 204800
#define MAXB 64

__device__ int    g_warm_idx[MAXN];
__device__ int    g_cold_idx[MAXN];
__device__ int    g_nwarm;
__device__ int    g_ncold;
__device__ double g_kl_sum;
__device__ float  g_sim[(size_t)MAXB * MAXN];
__device__ float  g_qn[MAXB * 256];
__device__ __nv_bfloat16 g_qnb[MAXB * 256];
__device__ float  g_rown[MAXN];           // |x|^2, cold rows (written by k_sim)
__device__ int    g_topidx[MAXB * 32];
__device__ float  g_cand_v[MAXB * 256];
__device__ int    g_cand_g[MAXB * 256];
__device__ __nv_bfloat16 g_Wh[256 * 256];
__device__ __nv_bfloat16 g_Wl[256 * 256];
__device__ __nv_bfloat16 g_Dh[256 * 128];
__device__ __nv_bfloat16 g_Dl[256 * 128];

// ---------------- helpers ----------------
__device__ __forceinline__ uint32_t pk2(__nv_bfloat16 a, __nv_bfloat16 b) {
    return (uint32_t)__bfloat16_as_ushort(a) | ((uint32_t)__bfloat16_as_ushort(b) << 16);
}
__device__ __forceinline__ uint32_t smem_u32(const void* p) {
    uint32_t a;
    asm("{ .reg .u64 t; cvta.to.shared.u64 t, %1; cvt.u32.u64 %0, t; }" : "=r"(a) : "l"(p));
    return a;
}

#define MMA16816(c, a, b) asm volatile( \
    "mma.sync.aligned.m16n8k16.row.col.f32.bf16.bf16.f32 " \
    "{%0,%1,%2,%3}, {%4,%5,%6,%7}, {%8,%9}, {%0,%1,%2,%3};" \
    : "+f"((c)[0]), "+f"((c)[1]), "+f"((c)[2]), "+f"((c)[3]) \
    : "r"((a)[0]), "r"((a)[1]), "r"((a)[2]), "r"((a)[3]), "r"((b)[0]), "r"((b)[1]))

__device__ __forceinline__ void ldm4(uint32_t addr, uint32_t r[4]) {
    asm volatile("ldmatrix.sync.aligned.m8n8.x4.shared.b16 {%0,%1,%2,%3}, [%4];"
                 : "=r"(r[0]), "=r"(r[1]), "=r"(r[2]), "=r"(r[3]) : "r"(addr));
}

#define TSTRIDE 72
#define MUSTRIDE 136
#define OFF_AH  0
#define OFF_AL  18432
#define OFF_BH  36864
#define OFF_BL  73728
#define OFF_MUH 110592
#define OFF_MUL 145408
#define DSMEM_SZ 180224

__device__ __forceinline__ void split_store4(char* smem, int m, int k, float4 v,
                                             int off_hi, int off_lo) {
    __nv_bfloat16 h0 = __float2bfloat16(v.x), h1 = __float2bfloat16(v.y);
    __nv_bfloat16 h2 = __float2bfloat16(v.z), h3 = __float2bfloat16(v.w);
    float l0 = v.x - __bfloat162float(h0), l1 = v.y - __bfloat162float(h1);
    float l2 = v.z - __bfloat162float(h2), l3 = v.w - __bfloat162float(h3);
    size_t base = (size_t)m * TSTRIDE + k;
    *(uint2*)(smem + off_hi + base * 2) = make_uint2(pk2(h0, h1), pk2(h2, h3));
    *(uint2*)(smem + off_lo + base * 2) =
        make_uint2(pk2(__float2bfloat16(l0), __float2bfloat16(l1)),
                   pk2(__float2bfloat16(l2), __float2bfloat16(l3)));
}

// ---------------- init + query norm ----------------
__global__ __launch_bounds__(256) void k_initq(const float* __restrict__ q, int D) {
    int b = blockIdx.x, t = threadIdx.x;
    if (b == 0 && t == 0) { g_nwarm = 0; g_ncold = 0; g_kl_sum = 0.0; }
    float ss = 0.f;
    for (int c = t; c < D; c += 256) { float v = q[(size_t)b * D + c]; ss += v * v; }
    __shared__ float red[256];
    red[t] = ss; __syncthreads();
    for (int s = 128; s > 0; s >>= 1) { if (t < s) red[t] += red[t + s]; __syncthreads(); }
    float scale = 1.f / (sqrtf(red[0]) + 1e-10f);
    for (int c = t; c < D; c += 256) {
        float v = q[(size_t)b * D + c] * scale;
        g_qn[(size_t)b * D + c] = v;
        g_qnb[(size_t)b * D + c] = __float2bfloat16(v);
    }
}

// ---------------- warp-aggregated tier partition ----------------
__global__ void k_partition(const int* __restrict__ tiers, int N) {
    int i = blockIdx.x * blockDim.x + threadIdx.x;
    bool in = i < N;
    int t = in ? tiers[i] : 0;
    unsigned m1 = __ballot_sync(0xffffffffu, t == 1);
    unsigned m2 = __ballot_sync(0xffffffffu, t == 2);
    int lane = threadIdx.x & 31;
    unsigned lt = (1u << lane) - 1u;
    if (t == 1) {
        int ldr = __ffs(m1) - 1;
        int base = 0;
        if (lane == ldr) base = atomicAdd(&g_nwarm, __popc(m1));
        base = __shfl_sync(m1, base, ldr);
        g_warm_idx[base + __popc(m1 & lt)] = i;
    } else if (t == 2) {
        int ldr = __ffs(m2) - 1;
        int base = 0;
        if (lane == ldr) base = atomicAdd(&g_ncold, __popc(m2));
        base = __shfl_sync(m2, base, ldr);
        g_cold_idx[base + __popc(m2 & lt)] = i;
    }
}

// ---------------- copy HOT rows only (warm<-k_warm, cold<-k_sim) -----------
__global__ __launch_bounds__(256) void k_copyhot(const float4* __restrict__ src,
                                                 float4* __restrict__ dst,
                                                 const int* __restrict__ tiers, long n4) {
    long i = (long)blockIdx.x * blockDim.x + threadIdx.x;
    if (i >= n4) return;
    int row = (int)(i >> 6);
    if (tiers[row] == 0) dst[i] = src[i];
}

// ---------------- weight pre-convert ----------------
__global__ __launch_bounds__(256) void k_wprep(const float* __restrict__ W_mu,
                                               const float* __restrict__ W_lv,
                                               const float* __restrict__ W_dec) {
    int idx = blockIdx.x * blockDim.x + threadIdx.x;
    if (idx < 65536) {
        int n = idx >> 8, k = idx & 255;
        float w = (n < 128) ? W_mu[(size_t)n * 256 + k] : W_lv[(size_t)(n - 128) * 256 + k];
        __nv_bfloat16 h = __float2bfloat16(w);
        g_Wh[idx] = h;
        g_Wl[idx] = __float2bfloat16(w - __bfloat162float(h));
    } else if (idx < 65536 + 32768) {
        int j = idx - 65536;
        float w = W_dec[j];
        __nv_bfloat16 h = __float2bfloat16(w);
        g_Dh[j] = h;
        g_Dl[j] = __float2bfloat16(w - __bfloat162float(h));
    }
}

// ---------------- approx sim + cold-row copy + fused row norms -------------
// 128 cold rows x 64 queries per block. While staging cold rows (fp32 load ->
// bf16 smem) we also: (a) store the fp32 row to new_features (the "copy" for
// cold rows), (b) accumulate per-row |x|^2 -> g_rown.
__global__ __launch_bounds__(256)
void k_sim(const float* __restrict__ feats, float* __restrict__ newf, int simld) {
    __shared__ char smem[128 * TSTRIDE * 2 + 64 * TSTRIDE * 2];
    const int OFF_B = 128 * TSTRIDE * 2;
    const int M = g_ncold;
    const int m0 = blockIdx.x * 128;
    if (m0 >= M) return;

    const int tid = threadIdx.x, wid = tid >> 5, lane = tid & 31;
    const int wm = wid >> 1, wn = wid & 1;
    const uint32_t sb = smem_u32(smem);

    float acc[2][4][4];
    #pragma unroll
    for (int mi = 0; mi < 2; mi++)
        #pragma unroll
        for (int ni = 0; ni < 4; ni++)
            #pragma unroll
            for (int j = 0; j < 4; j++) acc[mi][ni][j] = 0.f;

    const int aRow = (lane & 15), aColSel = (lane >> 4) << 3;
    const int bRow = (lane & 7) + ((lane & 16) >> 1), bColSel = lane & 8;
    const int gq = lane >> 2, qq = (lane & 3) * 2;

    int arows[8];
    float ssq[8];
    #pragma unroll
    for (int it = 0; it < 8; it++) {
        int r = m0 + ((tid + it * 256) >> 4);
        arows[it] = g_cold_idx[(r < M) ? r : m0];
        ssq[it] = 0.f;
    }

    for (int c = 0; c < 4; c++) {
        const int k0 = c * 64;
        #pragma unroll
        for (int it = 0; it < 8; it++) {
            int id = tid + it * 256;
            int m = id >> 4, kq = id & 15;
            float4 v = *(const float4*)(feats + (size_t)arows[it] * 256 + k0 + kq * 4);
            // cold-row copy into new_features (same data, fp32)
            *(float4*)(newf + (size_t)arows[it] * 256 + k0 + kq * 4) = v;
            ssq[it] += v.x * v.x + v.y 
* v.y + v.z * v.z + v.w * v.w;
            *(uint2*)(smem + ((size_t)m * TSTRIDE + kq * 4) * 2) =
                make_uint2(pk2(__float2bfloat16(v.x), __float2bfloat16(v.y)),
                           pk2(__float2bfloat16(v.z), __float2bfloat16(v.w)));
        }
        if (c == 3) {
            // finish |x|^2: 16 consecutive threads (kq 0..15) share a row
            #pragma unroll
            for (int it = 0; it < 8; it++) {
                float s = ssq[it];
                #pragma unroll
                for (int o = 8; o > 0; o >>= 1) s += __shfl_xor_sync(0xffffffffu, s, o);
                if ((tid & 15) == 0) g_rown[arows[it]] = s;
            }
        }
        #pragma unroll
        for (int it = 0; it < 2; it++) {
            int id = tid + it * 256;
            int n = id >> 3, u = id & 7;
            *(uint4*)(smem + OFF_B + ((size_t)n * TSTRIDE + u * 8) * 2) =
                *(const uint4*)(g_qnb + (size_t)n * 256 + k0 + u * 8);
        }
        __syncthreads();

        #pragma unroll
        for (int kk = 0; kk < 64; kk += 16) {
            uint32_t a[2][4];
            #pragma unroll
            for (int mi = 0; mi < 2; mi++) {
                uint32_t off = ((uint32_t)(wm * 32 + mi * 16 + aRow) * TSTRIDE + kk + aColSel) * 2;
                ldm4(sb + off, a[mi]);
            }
            #pragma unroll
            for (int np = 0; np < 2; np++) {
                uint32_t boff = ((uint32_t)(wn * 32 + np * 16 + bRow) * TSTRIDE + kk + bColSel) * 2;
                uint32_t bfr[4];
                ldm4(sb + OFF_B + boff, bfr);
                #pragma unroll
                for (int mi = 0; mi < 2; mi++) {
                    MMA16816(acc[mi][np * 2],     a[mi], &bfr[0]);
                    MMA16816(acc[mi][np * 2 + 1], a[mi], &bfr[2]);
                }
            }
        }
        __syncthreads();
    }

    #pragma unroll
    for (int mi = 0; mi < 2; mi++) {
        #pragma unroll
        for (int half = 0; half < 2; half++) {
            int rl = wm * 32 + mi * 16 + gq + half * 8;
            int j = m0 + rl;
            if (j >= M) continue;
            int grown = g_cold_idx[j];
            float inv = 1.f / (sqrtf(g_rown[grown]) + 1e-10f);
            #pragma unroll
            for (int ni = 0; ni < 4; ni++) {
                int q = wn * 32 + ni * 8 + qq;
                g_sim[(size_t)q * simld + j] = acc[mi][ni][half * 2 + 0] * inv;
                g_sim[(size_t)(q + 1) * simld + j] = acc[mi][ni][half * 2 + 1] * inv;
            }
        }
    }
}

// ---------------- top-k stage 1: per-slice top-32 --------------------------
__global__ __launch_bounds__(256) void k_topk1(int simld) {
    const int sl = blockIdx.x, b = blockIdx.y;
    const int ncold = g_ncold;
    const int t = threadIdx.x, lane = t & 31, warp = t >> 5;
    const int s0 = (int)(((long)ncold * sl) >> 3);
    const int s1 = (int)(((long)ncold * (sl + 1)) >> 3);

    float tv[4]; int tg[4];
    #pragma unroll
    for (int s = 0; s < 4; s++) { tv[s] = -INFINITY; tg[s] = 0x7fffffff; }

    const float* srow = g_sim + (size_t)b * simld;
    int j = s0 + t;
    for (; j + 768 < s1; j += 1024) {
        float v0 = srow[j], v1 = srow[j + 256], v2 = srow[j + 512], v3 = srow[j + 768];
        #pragma unroll
        for (int u = 0; u < 4; u++) {
            float v = (u == 0) ? v0 : (u == 1) ? v1 : (u == 2) ? v2 : v3;
            int jj = j + u * 256;
            if (v > tv[3]) {
                tv[3] = v; tg[3] = g_cold_idx[jj];
                #pragma unroll
                for (int s = 2; s >= 0; s--)
                    if (tv[s + 1] > tv[s]) {
                        float x = tv[s]; tv[s] = tv[s + 1]; tv[s + 1] = x;
                        int y = tg[s]; tg[s] = tg[s + 1]; tg[s + 1] = y;
                    }
            }
        }
    }
    for (; j < s1; j += 256) {
        float v = srow[j];
        if (v > tv[3]) {
            tv[3] = v; tg[3] = g_cold_idx[j];
            #pragma unroll
            for (int s = 2; s >= 0; s--)
                if (tv[s + 1] > tv[s]) {
                    float x = tv[s]; tv[s] = tv[s + 1]; tv[s + 1] = x;
                    int y = tg[s]; tg[s] = tg[s + 1]; tg[s + 1] = y;
                }
        }
    }

    __shared__ float wv[8];
    __shared__ int   wg[8];
    __shared__ int   wing_s;

    float* outv = g_cand_v + ((size_t)b * 8 + sl) * 32;
    int*   outg = g_cand_g + ((size_t)b * 8 + sl) * 32;

    for (int sel = 0; sel < 32; sel++) {
        float v = tv[0]; int g = tg[0];
        #pragma unroll
        for (int o = 16; o > 0; o >>= 1) {
            float ov = __shfl_xor_sync(0xffffffffu, v, o);
            int   og = __shfl_xor_sync(0xffffffffu, g, o);
            if (ov > v || (ov == v && og < g)) { v = ov; g = og; }
        }
        if (lane == 0) { wv[warp] = v; wg[warp] = g; }
        __syncthreads();
        if (t == 0) {
            float bv = wv[0]; int bg = wg[0];
            #pragma unroll
            for (int u = 1; u < 8; u++)
                if (wv[u] > bv || (wv[u] == bv && wg[u] < bg)) { bv = wv[u]; bg = wg[u]; }
            wing_s = bg;
            outv[sel] = bv; outg[sel] = bg;
        }
        __syncthreads();
        if (tg[0] == wing_s) {
            tv[0] = tv[1]; tg[0] = tg[1];
            tv[1] = tv[2]; tg[1] = tg[2];
            tv[2] = tv[3]; tg[2] = tg[3];
            tv[3] = -INFINITY; tg[3] = 0x7fffffff;
        }
        __syncthreads();
    }
}

// ---------------- top-k stage 2: merge + exact fp32 rescore ----------------
__global__ __launch_bounds__(256) void k_topk2(const float* __restrict__ feats,
                                               int k, float* __restrict__ out_idx_f) {
    const int b = blockIdx.x;
    const int t = threadIdx.x, lane = t & 31, warp = t >> 5;

    float v = g_cand_v[(size_t)b * 256 + t];
    int   g = g_cand_g[(size_t)b * 256 + t];

    __shared__ float wv[8];
    __shared__ int   wg[8];
    __shared__ int   wing_s;
    __shared__ int   cgid[32];
    __shared__ float rsv[32];

    for (int sel = 0; sel < 32; sel++) {
        float mv = v; int mg = g;
        #pragma unroll
        for (int o = 16; o > 0; o >>= 1) {
            float ov = __shfl_xor_sync(0xffffffffu, mv, o);
            int   og = __shfl_xor_sync(0xffffffffu, mg, o);
            if (ov > mv || (ov == mv && og < mg)) { mv = ov; mg = og; }
        }
        if (lane == 0) { wv[warp] = mv; wg[warp] = mg; }
        __syncthreads();
        if (t == 0) {
            float bv = wv[0]; int bg = wg[0];
            #pragma unroll
            for (int u = 1; u < 8; u++)
                if (wv[u] > bv || (wv[u] == bv && wg[u] < bg)) { bv = wv[u]; bg = wg[u]; }
            wing_s = bg;
            cgid[sel] = bg;
        }
        __syncthreads();
        if (g == wing_s) { v = -INFINITY; g = 0x7fffffff; }
        __syncthreads();
    }

    {
        int c = t >> 3, e = t & 7;
        int gg = cgid[c];
        float part = 0.f;
        if (gg != 0x7fffffff) {
            const float* fr = feats + (size_t)gg * 256 + e * 32;
            const float* qr = g_qn + (size_t)b * 256 + e * 32;
            #pragma unroll
            for (int x = 0; x < 32; x += 4) {
                float4 f = *(const float4*)(fr + x);
                float4 qv = *(const float4*)(qr + x);
                part += f.x * qv.x + f.y * qv.y + f.z * qv.z + f.w * qv.w;
            }
        }
        #pragma unroll
        for (int o = 4; o > 0; o >>= 1) part += __shfl_xor_sync(0xffffffffu, part, o);
        if (e == 0)
            rsv[c] = (gg != 0x7fffffff) ? part / (sqrtf(g_rown[gg]) + 1e-10f) : -INFINITY;
    }
    __syncthreads();

    if (t < 32) {
        float vv = rsv[t]; int gg = cgid[t];
        int rank = 0;
        #pragma unroll
        for (int j2 = 0; j2 < 32; j2++) {
            float vj = rsv[j2]; int gj = cgid[j2];
            if (vj > vv || (vj == vv && gj < gg)) rank++;
        }
        if (rank < k) {
            g_topidx[b * 32 + rank] = gg;
            out_idx_f[(size_t)b * k + rank] = (float)gg;
        }
    }
}

// ---------------- fused warm pipeline: balanced mu/lv per warp --------------
// Phase 1: every warp covers 32 mu cols (3-pass hi/lo) + 32 lv cols (1-pass),
// equalizing the MMA critical path (was: mu warps 3x the work of lv warps).
__global__ __launch_bounds__(512)
void k_warm(const float* __restrict__ feats,
            const float* __restrict__ b_mu, const float* __restrict__ b_lv,
            const float* __restrict__ b_dec, float* __restrict__ newf) {
    extern __shared__ char smem[];
    const int M = g_nwarm;
    const int m0 = blockIdx.x * 128;
    if (m0 >= M) return;

    const int tid = threadIdx.x, wid = tid >> 5, lane = tid & 31;
    const int wm = wid >> 2, wn = wid & 3;
    const uint32_t sb = smem_u32(smem);

    float acc[2][8][4];
    #pragma unroll
    for (int mi = 0; mi < 2; mi++)
        #pragma unroll
        for (int ni = 0; ni < 8; ni++)
            #pragma unroll
            for (int j = 0; j < 4; j++) acc[mi][ni][j] = 0.f;

    const int aRow = (lane & 15), aColSel = (lane >> 4) << 3;
    const int bRow = (lane & 7) + ((lane & 16) >> 1), bColSel = lane & 8;
    const int gq = lane >> 2, qq = (lane & 3) * 2;

    int arows[4];
    #pragma unroll
    for (int it = 0; it < 4; it++) {
        int r = m0 + ((tid + it * 512) >> 4);
        arows[it] = g_warm_idx[(r < M) ? r : m0];
    }

    // ===== phase 1: [mu|lv] balanced =====
    for (int c = 0; c < 4; c++) {
        const int k0 = c * 64;
        #pragma unroll
        for (int it = 0; it < 4; it++) {
            int id = tid + it * 512;
            float4 v = *(const float4*)(feats + (size_t)arows[it] * 256 + k0 + (id & 15) * 4);
            split_store4(smem, id >> 4, (id & 15) * 4, v, OFF_AH, OFF_AL);
        }
        #pragma unroll
        for (int it = 0; it < 4; it++) {
            int id = tid + it * 512;
            int n = id >> 3, q = id & 7;
            size_t src = (size_t)n * 256 + k0 + q * 8;
            size_t dst = ((size_t)n * TSTRIDE + q * 8) * 2;
            *(uint4*)(smem + OFF_BH + dst) = *(const uint4*)(g_Wh + src);
            *(uint4*)(smem + OFF_BL + dst) = *(const uint4*)(g_Wl + src);
        }
        __syncthreads();

        #pragma unroll
        for (int kk = 0; kk < 64; kk += 16) {
            uint32_t ah[2][4], al[2][4];
            #pragma unroll
            for (int mi = 0; mi < 2; mi++) {
                uint32_t off = ((uint32_t)(wm * 32 + mi * 16 + aRow) * TSTRIDE + kk + aColSel) * 2;
                ldm4(sb + OFF_AH + off, ah[mi]);
                ldm4(sb + OFF_AL + off, al[mi]);
            }
            #pragma unroll
            for (int np = 0; np < 4; np++) {
                const bool mu_np = (np < 2);
                int n0 = mu_np ? (wn * 32 + np * 16) : (128 + wn * 32 + (np - 2) * 16);
                uint32_t boff = ((uint32_t)(n0 + bRow) * TSTRIDE + kk + bColSel) * 2;
                uint32_t bh[4], bl[4];
                ldm4(sb + OFF_BH + boff, bh);
                if (mu_np) ldm4(sb + OFF_BL + boff, bl);
                #pragma unroll
                for (int mi = 0; mi < 2; mi++) {
                    MMA16816(acc[mi][np * 2],     ah[mi], &bh[0]);
                    MMA16816(acc[mi][np * 2 + 1], ah[mi], &bh[2]);
                    if (mu_np) {
                        MMA16816(acc[mi][np * 2],     al[mi], &bh[0]);
                        MMA16816(acc[mi][np * 2],     ah[mi], &bl[0]);
                        MMA16816(acc[mi][np * 2 + 1], al[mi], &bh[2]);
                        MMA16816(acc[mi][np * 2 + 1], ah[mi], &bl[2]);
                    }
                }
            }
        }
        __syncthreads();
    }

    // ===== epilogue 1: ni<4 = mu cols (wn*32+ni*8), ni>=4 = lv cols ========
    float kl = 0.f;
    #pragma unroll
    for (int mi = 0; mi < 2; mi++) {
        #pragma unroll
        for (int half = 0; half < 2; half++) {
            int rl = wm * 32 + mi * 16 + gq + half * 8;
            int grow = m0 + rl;
            bool valid = grow < M;
            #pragma unroll
            for (int ni = 0; ni < 8; ni++) {
                const bool is_lv = (ni >= 4);
                int cl = wn * 32 + (is_lv ? (ni - 4) : ni) * 8 + qq;
                float bias0 = is_lv ? b_lv[cl] : b_mu[cl];
                float bias1 = is_lv ? b_lv[cl + 1] : b_mu[cl + 1];
                float v0 = acc[mi][ni][half * 2 + 0] + bias0;
                float v1 = acc[mi][ni][half * 2 + 1] + bias1;
                if (!is_lv) {
                    __nv_bfloat16 h0 = __float2bfloat16(v0), h1 = __float2bfloat16(v1);
                    float l0 = v0 - __bfloat162float(h0), l1 = v1 - __bfloat162float(h1);
                    uint32_t o = ((uint32_t)rl * MUSTRIDE + cl) * 2;
                    *(uint32_t*)(smem + OFF_MUH + o) = pk2(h0, h1);
                    *(uint32_t*)(smem + OFF_MUL + o) = pk2(__float2bfloat16(l0), __float2bfloat16(l1));
                    if (valid) kl += 0.5f * (v0 * v0 + v1 * v1) - 1.0f;
                } else if (valid) {
                    kl += 0.5f * (expf(v0) + expf(v1)) - 0.5f * (v0 + v1);
                }
            }
        }
    }
    #pragma unroll
    for (int o = 16; o > 0; o >>= 1) kl += __shfl_xor_sync(0xffffffffu, kl, o);
    if (lane == 0 && kl != 0.f) atomicAdd(&g_kl_sum, (double)kl);
    __syncthreads();

    // ===== phase 2: dec = mu @ Wdec^T (3-pass, all warps) =====
    #pragma unroll
    for (int mi = 0; mi < 2; mi++)
        #pragma unroll
        for (int ni = 0; ni < 8; ni++)
            #pragma unroll
            for (int j = 0; j < 4; j++) acc[mi][ni][j] = 0.f;

    for (int c = 0; c < 2; c++) {
        const int k0 = c * 64;
        #pragma unroll
        for (int it = 0; it < 4; it++) {
            int id = tid + it * 512;
            int n = id >> 3, q = id & 7;
            size_t src = (size_t)n * 128 + k0 + q * 8;
            size_t dst = ((size_t)n * TSTRIDE + q * 8) * 2;
            *(uint4*)(smem + OFF_BH + dst) = *(const uint4*)(g_Dh + src);
            *(uint4*)(smem + OFF_BL + dst) = *(const uint4*)(g_Dl + src);
        }
        __syncthreads();

        #pragma unroll
        for (int kk = 0; kk < 64; kk += 16) {
            uint32_t ah[2][4], al[2][4];
            #pragma unroll
            for (int mi = 0; mi < 2; mi++) {
                uint32_t off = ((uint32_t)(wm * 32 + mi * 16 + aRow) * MUSTRIDE + k0 + kk + aColSel) * 2;
                ldm4(sb + OFF_MUH + off, ah[mi]);
                ldm4(sb + OFF_MUL + off, al[mi]);
            }
            #pragma unroll
            for (int np = 0; np < 4; np++) {
                int n0 = wn * 64 + np * 16;
                uint32_t boff = ((uint32_t)(n0 + bRow) * TSTRIDE + kk + bColSel) * 2;
                uint32_t bh[4], bl[4];
                ldm4(sb + OFF_BH + boff, bh);
                ldm4(sb + OFF_BL + boff, bl);
                #pragma unroll
                for (int mi = 0; mi < 2; mi++) {
                    MMA16816(acc[mi][np * 2],     ah[mi], &bh[0]);
                    MMA16816(acc[mi][np * 2],     al[mi], &bh[0]);
                    MMA16816(acc[mi][np * 2],     ah[mi], &bl[0]);
                    MMA16816(acc[mi][np * 2 + 1], ah[mi], &bh[2]);
                    MMA16816(acc[mi][np * 2 + 1], al[mi], &bh[2]);
                    MMA16816(acc[mi][np * 2 + 1], ah[mi], &bl[2]);
                }
            }
        }
        __syncthreads();
    }

    #pragma unroll
    for (int mi = 0; mi < 2; mi++) {
        #pragma unroll
        for (int half = 0; half < 2; half++) {
            int grow = m0 + wm * 32 + mi * 16 + gq + half * 8;
            if (grow >= M) continue;
            int wr = g_warm_idx[grow];
            #pragma unroll
            for (int ni = 0; ni < 8; ni++) {
                int col = wn * 64 + ni * 8 + qq;
                float2 v = make_float2(acc[mi][ni][half * 2 + 0] + b_dec[col],
                                       acc[mi][ni][half * 2 + 1] + b_dec[col + 1]);
                *(float2*)(newf + (size_t)wr * 256 + col) = v;
            }
        }
    }
}

// ---------------- gather + kl finalize ----------------
__global__ __launch_bounds__(256) void k_gather(const float* __restrict__ newf,
                                                float* __restrict__ ret, int D, int k,
                                                float* __restrict__ klp, int W) {
    int r = blockIdx.x;
    if (r == 0 && threadIdx.x == 0) {
        int n = g_nwarm > 0 ? g_nwarm : 1;
        *klp = (float)(g_kl_sum / ((double)n * (double)W));
    }
    int row = g_topidx[(r / k) * 32 + (r % k)];
    const float* s = newf + (size_t)row * D;
    float* d = ret + (size_t)r * D;
    for (int c = threadIdx.x; c < D; c += blockDim.x) d[c] = s[c];
}

extern "C" void kernel_launch(void* const* d_in, const int* in_sizes, int n_in,
                              void* d_out, int out_size) {
    const float* feats = (const float*)d_in[0];
    const int*   tiers = (const int*)d_in[1];
    const float* query = (const float*)d_in[2];
    const float* W_mu  = (const float*)d_in[3];
    const float* b_mu  = (const float*)d_in[4];
    const float* W_lv  = (const float*)d_in[5];
    const float* b_lv  = (const float*)d_in[6];
    const float* W_dec = (const float*)d_in[7];
    const float* b_dec = (const float*)d_in[8];

    const int N = in_sizes[1];
    const int D = in_sizes[0] / N;
    const int B = in_sizes[2] / D;
    const int W = in_sizes[4];
    const long k = ((long)out_size - (long)N * D - 1) / ((long)B * (D + 1));

    float* out   = (float*)d_out;
    float* newf  = out;
    float* klp   = out + (size_t)N * D;
    float* ret   = klp + 1;
    float* tidxf = ret + (size_t)B * k * D;

    cudaFuncSetAttribute(k_warm, cudaFuncAttributeMaxDynamicSharedMemorySize, DSMEM_SZ);

    const int gy = (N + 127) / 128;
    long n4 = (long)N * D / 4;

    // order: k_warm is the 4th launch -> profiled by ncu (-s 5 -c 1)
    k_initq<<<B, 256>>>(query, D);
    k_partition<<<(N + 255) / 256, 256>>>(tiers, N);
    k_wprep<<<384, 256>>>(W_mu, W_lv, W_dec);
    k_warm<<<gy, 512, DSMEM_SZ>>>(feats, b_mu, b_lv, b_dec, newf);

    k_copyhot<<<(unsigned)((n4 + 255) / 256), 256>>>((const float4*)feats, (float4*)newf, tiers, n4);
    k_sim<<<gy, 256>>>(feats, newf, N);
    k_topk1<<<dim3(8, B), 256>>>(N);
    k_topk2<<<B, 256>>>(feats, (int)k, tidxf);
    k_gather<<<B * (int)k, 256>>>(newf, ret, D, (int)k, klp, W);
}

// round 16
// speedup vs baseline: 1.1953x; 1.1953x over previous
#include <cuda_runtime.h>
#include <cuda_bf16.h>
#include <math.h>
#include <stdint.h>

// ---------------- static scratch (no allocations allowed) ----------------
#define MAXN 204800
#define MAXB 64

__device__ int    g_warm_idx[MAXN];
__device__ int    g_cold_idx[MAXN];
__device__ int    g_nwarm;
__device__ int    g_ncold;
__device__ double g_kl_sum;
__device__ float  g_sim[(size_t)MAXB * MAXN];
__device__ float  g_qn[MAXB * 256];
__device__ __nv_bfloat16 g_qnb[MAXB * 256];
__device__ float  g_rown[MAXN];
__device__ int    g_topidx[MAXB * 32];
__device__ float  g_cand_v[MAXB * 256];
__device__ int    g_cand_g[MAXB * 256];
__device__ __nv_bfloat16 g_Wh[256 * 256];
__device__ __nv_bfloat16 g_Wl[256 * 256];
__device__ __nv_bfloat16 g_Dh[256 * 128];
__device__ __nv_bfloat16 g_Dl[256 * 128];

// ---------------- helpers ----------------
__device__ __forceinline__ uint32_t pk2(__nv_bfloat16 a, __nv_bfloat16 b) {
    return (uint32_t)__bfloat16_as_ushort(a) | ((uint32_t)__bfloat16_as_ushort(b) << 16);
}
__device__ __forceinline__ uint32_t smem_u32(const void* p) {
    uint32_t a;
    asm("{ .reg .u64 t; cvta.to.shared.u64 t, %1; cvt.u32.u64 %0, t; }" : "=r"(a) : "l"(p));
    return a;
}

#define MMA16816(c, a, b) asm volatile( \
    "mma.sync.aligned.m16n8k16.row.col.f32.bf16.bf16.f32 " \
    "{%0,%1,%2,%3}, {%4,%5,%6,%7}, {%8,%9}, {%0,%1,%2,%3};" \
    : "+f"((c)[0]), "+f"((c)[1]), "+f"((c)[2]), "+f"((c)[3]) \
    : "r"((a)[0]), "r"((a)[1]), "r"((a)[2]), "r"((a)[3]), "r"((b)[0]), "r"((b)[1]))

__device__ __forceinline__ void ldm4(uint32_t addr, uint32_t r[4]) {
    asm volatile("ldmatrix.sync.aligned.m8n8.x4.shared.b16 {%0,%1,%2,%3}, [%4];"
                 : "=r"(r[0]), "=r"(r[1]), "=r"(r[2]), "=r"(r[3]) : "r"(addr));
}

#define TSTRIDE 72
#define MUSTRIDE 136
#define OFF_AH  0
#define OFF_AL  18432
#define OFF_BH  36864
#define OFF_BL  73728
#define OFF_MUH 110592
#define OFF_MUL 145408
#define DSMEM_SZ 180224

__device__ __forceinline__ void split_store4(char* smem, int m, int k, float4 v,
                                             int off_hi, int off_lo) {
    __nv_bfloat16 h0 = __float2bfloat16(v.x), h1 = __float2bfloat16(v.y);
    __nv_bfloat16 h2 = __float2bfloat16(v.z), h3 = __float2bfloat16(v.w);
    float l0 = v.x - __bfloat162float(h0), l1 = v.y - __bfloat162float(h1);
    float l2 = v.z - __bfloat162float(h2), l3 = v.w - __bfloat162float(h3);
    size_t base = (size_t)m * TSTRIDE + k;
    *(uint2*)(smem + off_hi + base * 2) = make_uint2(pk2(h0, h1), pk2(h2, h3));
    *(uint2*)(smem + off_lo + base * 2) =
        make_uint2(pk2(__float2bfloat16(l0), __float2bfloat16(l1)),
                   pk2(__float2bfloat16(l2), __float2bfloat16(l3)));
}

// ---------------- init + query norm ----------------
__global__ __launch_bounds__(256) void k_initq(const float* __restrict__ q, int D) {
    int b = blockIdx.x, t = threadIdx.x;
    if (b == 0 && t == 0) { g_nwarm = 0; g_ncold = 0; g_kl_sum = 0.0; }
    float ss = 0.f;
    for (int c = t; c < D; c += 256) { float v = q[(size_t)b * D + c]; ss += v * v; }
    __shared__ float red[256];
    red[t] = ss; __syncthreads();
    for (int s = 128; s > 0; s >>= 1) { if (t < s) red[t] += red[t + s]; __syncthreads(); }
    float scale = 1.f / (sqrtf(red[0]) + 1e-10f);
    for (int c = t; c < D; c += 256) {
        float v = q[(size_t)b * D + c] * scale;
        g_qn[(size_t)b * D + c] = v;
        g_qnb[(size_t)b * D + c] = __float2bfloat16(v);
    }
}

// ---------------- warp-aggregated tier partition ----------------
__global__ void k_partition(const int* __restrict__ tiers, int N) {
    int i = blockIdx.x * blockDim.x + threadIdx.x;
    bool in = i < N;
    int t = in ? tiers[i] : 0;
    unsigned m1 = __ballot_sync(0xffffffffu, t == 1);
    unsigned m2 = __ballot_sync(0xffffffffu, t == 2);
    int lane = threadIdx.x & 31;
    unsigned lt = (1u << lane) - 1u;
    if (t == 1) {
        int ldr = __ffs(m1) - 1;
        int base = 0;
        if (lane == ldr) base = atomicAdd(&g_nwarm, __popc(m1));
        base = __shfl_sync(m1, base, ldr);
        g_warm_idx[base + __popc(m1 & lt)] = i;
    } else if (t == 2) {
        int ldr = __ffs(m2) - 1;
        int base = 0;
        if (lane == ldr) base = atomicAdd(&g_ncold, __popc(m2));
        base = __shfl_sync(m2, base, ldr);
        g_cold_idx[base + __popc(m2 & lt)] = i;
    }
}

// ---------------- copy (skip warm) + fused per-row |x|^2 (R14 proven) ------
__global__ __launch_bounds__(256) void k_copy4(const float4* __restrict__ src,
                                               float4* __restrict__ dst,
                                               const int* __restrict__ tiers, long n4) {
    long i = (long)blockIdx.x * blockDim.x + threadIdx.x;
    int t = threadIdx.x;
    float4 v = make_float4(0.f, 0.f, 0.f, 0.f);
    if (i < n4) {
        v = src[i];
        int row = (int)(i >> 6);
        if (tiers[row] != 1) dst[i] = v;
    }
    float ss = v.x * v.x + v.y * v.y + v.z * v.z + v.w * v.w;
    #pragma unroll
    for (int o = 16; o > 0; o >>= 1) ss += __shfl_xor_sync(0xffffffffu, ss, o);
    __shared__ float wred[8];
    if ((t & 31) == 0) wred[t >> 5] = ss;
    __syncthreads();
    if (t < 4) {
        long r0 = ((long)blockIdx.x * 256) >> 6;
        if (r0 + t < (n4 >> 6)) g_rown[r0 + t] = wred[2 * t] + wred[2 * t + 1];
    }
}

// ---------------- weight pre-convert ----------------
__global__ __launch_bounds__(256) void k_wprep(const float* __restrict__ W_mu,
                                               const float* __restrict__ W_lv,
                                               const float* __restrict__ W_dec) {
    int idx = blockIdx.x * blockDim.x + threadIdx.x;
    if (idx < 65536) {
        int n = idx >> 8, k = idx & 255;
        float w = (n < 128) ? W_mu[(size_t)n * 256 + k] : W_lv[(size_t)(n - 128) * 256 + k];
        __nv_bfloat16 h = __float2bfloat16(w);
        g_Wh[idx] = h;
        g_Wl[idx] = __float2bfloat16(w - __bfloat162float(h));
    } else if (idx < 65536 + 32768) {
        int j = idx - 65536;
        float w = W_dec[j];
        __nv_bfloat16 h = __float2bfloat16(w);
        g_Dh[j] = h;
        g_Dl[j] = __float2bfloat16(w - __bfloat162float(h));
    }
}

// ---------------- approx sim: single-pass bf16 HMMA (R14 proven) -----------
__global__ __launch_bounds__(256)
void k_sim(const float* __restrict__ feats, int simld) {
    __shared__ char smem[128 * TSTRIDE * 2 + 64 * TSTRIDE * 2];
    const int OFF_B = 128 * TSTRIDE * 2;
    const int M = g_ncold;
    const int m0 = blockIdx.x * 128;
    if (m0 >= M) return;

    const int tid = threadIdx.x, wid = tid >> 5, lane = tid & 31;
    const int wm = wid >> 1, wn = wid & 1;
    const uint32_t sb = smem_u32(smem);

    float acc[2][4][4];
    #pragma unroll
    for (int mi = 0; mi < 2; mi++)
        #pragma unroll
        for (int ni = 0; ni < 4; ni++)
            #pragma unroll
            for (int j = 0; j < 4; j++) acc[mi][ni][j] = 0.f;

    const int aRow = (lane & 15), aColSel = (lane >> 4) << 3;
    const int bRow = (lane & 7) + ((lane & 16) >> 1), bColSel = lane & 8;
    const int gq = lane >> 2, qq = (lane & 3) * 2;

    int arows[8];
    #pragma unroll
    for (int it = 0; it < 8; it++) {
        int r = m0 + ((tid + it * 256) >> 4);
        arows[it] = g_cold_idx[(r < M) ? r : m0];
    }

    for (int c = 0; c < 4; c++) {
        const int k0 = c * 64;
        #pragma unroll
        for (int it = 0; it < 8; it++) {
            int id = tid + it * 256;
            int m = id >> 4, kq = id & 15;
            float4 v = *(const float4*)(feats + (size_t)arows[it] * 256 + k0 + kq * 4);
            *(uint2*)(smem + ((size_t)m * TSTRIDE + kq * 4) * 2) =
                make_uint2(pk2(__float2bfloat16(v.x), __float2bfloat16(v.y)),
                           pk2(__float2bfloat16(v.z), __float2bfloat16(v.w)));
        }
        #pragma unroll
        for (int it = 0; it < 2; it++) {
            int id = tid + it * 256;
            int n = id >> 3, u = id & 7;
            *(uint4*)(smem + OFF_B + ((size_t)n * TSTRIDE + u * 8) * 2) =
                *(const uint4*)(g_qnb + (size_t)n * 256 + k0 + u * 8);
        }
        __syncthreads();

        #pragma unroll
        for (int kk = 0; kk < 64; kk += 16) {
            uint32_t a[2][4];
            #pragma unroll
            for (int mi = 0; mi < 2; mi++) {
                uint32_t off = ((uint32_t)(wm * 32 + mi * 16 + aRow) * TSTRIDE + kk + aColSel) * 2;
                ldm4(sb + off, a[mi]);
            }
            #pragma unroll
            for (int np = 0; np < 2; np++) {
                uint32_t boff = ((uint32_t)(wn * 32 + np * 16 + bRow) * TSTRIDE + kk + bColSel) * 2;
                uint32_t bfr[4];
                ldm4(sb + OFF_B + boff, bfr);
                #pragma unroll
                for (int mi = 0; mi < 2; mi++) {
                    MMA16816(acc[mi][np * 2],     a[mi], &bfr[0]);
                    MMA16816(acc[mi][np * 2 + 1], a[mi], &bfr[2]);
                }
            }
        }
        __syncthreads();
    }

    #pragma unroll
    for (int mi = 0; mi < 2; mi++) {
        #pragma unroll
        for (int half = 0; half < 2; half++) {
            int rl = wm * 32 + mi * 16 + gq + half * 8;
            int j = m0 + rl;
            if (j >= M) continue;
            int grown = g_cold_idx[j];
            float inv = 1.f / (sqrtf(g_rown[grown]) + 1e-10f);
            #pragma unroll
            for (int ni = 0; ni < 4; ni++) {
                int q = wn * 32 + ni * 8 + qq;
                g_sim[(size_t)q * simld + j] = acc[mi][ni][half * 2 + 0] * inv;
                g_sim[(size_t)(q + 1) * simld + j] = acc[mi][ni][half * 2 + 1] * inv;
            }
        }
    }
}

// ---------------- top-k stage 1: per-slice top-32 --------------------------
__global__ __launch_bounds__(256) void k_topk1(int simld) {
    const int sl = blockIdx.x, b = blockIdx.y;
    const int ncold = g_ncold;
    const int t = threadIdx.x, lane = t & 31, warp = t >> 5;
    const int s0 = (int)(((long)ncold * sl) >> 3);
    const int s1 = (int)(((long)ncold * (sl + 1)) >> 3);

    float tv[4]; int tg[4];
    #pragma unroll
    for (int s = 0; s < 4; s++) { tv[s] = -INFINITY; tg[s] = 0x7fffffff; }

    const float* srow = g_sim + (size_t)b * simld;
    int j = s0 + t;
    for (; j + 768 < s1; j += 1024) {
        float v0 = srow[j], v1 = srow[j + 256], v2 = srow[j + 512], v3 = srow[j + 768];
        #pragma unroll
        for (int u = 0; u < 4; u++) {
            float v = (u == 0) ? v0 : (u == 1) ? v1 : (u == 2) ? v2 : v3;
            int jj = j + u * 256;
            if (v > tv[3]) {
                tv[3] = v; tg[3] = g_cold_idx[jj];
                #pragma unroll
                for (int s = 2; s >= 0; s--)
                    if (tv[s + 1] > tv[s]) {
                        float x = tv[s]; tv[s] = tv[s + 1]; tv[s + 1] = x;
                        int y = tg[s]; tg[s] = tg[s + 1]; tg[s + 1] = y;
                    }
            }
        }
    }
    for (; j < s1; j += 256) {
        float v = srow[j];
        if (v > tv[3]) {
            tv[3] = v; tg[3] = g_cold_idx[j];
            #pragma unroll
            for (int s = 2; s >= 0; s--)
                if (tv[s + 1] > tv[s]) {
                    float x = tv[s]; tv[s] = tv[s + 1]; tv[s + 1] = x;
                    int y = tg[s]; tg[s] = tg[s + 1]; tg[s + 1] = y;
                }
        }
    }

    __shared__ float wv[8];
    __shared__ int   wg[8];
    __shared__ int   wing_s;

    float* outv = g_cand_v + ((size_t)b * 8 + sl) * 32;
    int*   outg = g_cand_g + ((size_t)b * 8 + sl) * 32;

    for (int sel = 0; sel < 32; sel++) {
        float v = tv[0]; int g = tg[0];
        #pragma unroll
        for (int o = 16; o > 0; o >>= 1) {
            float ov = __shfl_xor_sync(0xffffffffu, v, o);
            int   og = __shfl_xor_sync(0xffffffffu, g, o);
            if (ov > v || (ov == v && og < g)) { v = ov; g = og; }
        }
        if (lane == 0) { wv[warp] = v; wg[warp] = g; }
        __syncthreads();
        if (t == 0) {
            float bv = wv[0]; int bg = wg[0];
            #pragma unroll
            for (int u = 1; u < 8; u++)
                if (wv[u] > bv || (wv[u] == bv && wg[u] < bg)) { bv = wv[u]; bg = wg[u]; }
            wing_s = bg;
            outv[sel] = bv; outg[sel] = bg;
        }
        __syncthreads();
        if (tg[0] == wing_s) {
            tv[0] = tv[1]; tg[0] = tg[1];
            tv[1] = tv[2]; tg[1] = tg[2];
            tv[2] = tv[3]; tg[2] = tg[3];
            tv[3] = -INFINITY; tg[3] = 0x7fffffff;
        }
        __syncthreads();
    }
}

// ---------------- top-k stage 2: merge + exact fp32 rescore ----------------
__global__ __launch_bounds__(256) void k_topk2(const float* __restrict__ feats,
                                               int k, float* __restrict__ out_idx_f) {
    const int b = blockIdx.x;
    const int t = threadIdx.x, lane = t & 31, warp = t >> 5;

    float v = g_cand_v[(size_t)b * 256 + t];
    int   g = g_cand_g[(size_t)b * 256 + t];

    __shared__ float wv[8];
    __shared__ int   wg[8];
    __shared__ int   wing_s;
    __shared__ int   cgid[32];
    __shared__ float rsv[32];

    for (int sel = 0; sel < 32; sel++) {
        float mv = v; int mg = g;
        #pragma unroll
        for (int o = 16; o > 0; o >>= 1) {
            float ov = __shfl_xor_sync(0xffffffffu, mv, o);
            int   og = __shfl_xor_sync(0xffffffffu, mg, o);
            if (ov > mv || (ov == mv && og < mg)) { mv = ov; mg = og; }
        }
        if (lane == 0) { wv[warp] = mv; wg[warp] = mg; }
        __syncthreads();
        if (t == 0) {
            float bv = wv[0]; int bg = wg[0];
            #pragma unroll
            for (int u = 1; u < 8; u++)
                if (wv[u] > bv || (wv[u] == bv && wg[u] < bg)) { bv = wv[u]; bg = wg[u]; }
            wing_s = bg;
            cgid[sel] = bg;
        }
        __syncthreads();
        if (g == wing_s) { v = -INFINITY; g = 0x7fffffff; }
        __syncthreads();
    }

    {
        int c = t >> 3, e = t & 7;
        int gg = cgid[c];
        float part = 0.f;
        if (gg != 0x7fffffff) {
            const float* fr = feats + (size_t)gg * 256 + e * 32;
            const float* qr = g_qn + (size_t)b * 256 + e * 32;
            #pragma unroll
            for (int x = 0; x < 32; x += 4) {
                float4 f = *(const float4*)(fr + x);
                float4 qv = *(const float4*)(qr + x);
                part += f.x * qv.x + f.y * qv.y + f.z * qv.z + f.w * qv.w;
            }
        }
        #pragma unroll
        for (int o = 4; o > 0; o >>= 1) part += __shfl_xor_sync(0xffffffffu, part, o);
        if (e == 0)
            rsv[c] = (gg != 0x7fffffff) ? part / (sqrtf(g_rown[gg]) + 1e-10f) : -INFINITY;
    }
    __syncthreads();

    if (t < 32) {
        float vv = rsv[t]; int gg = cgid[t];
        int rank = 0;
        #pragma unroll
        for (int j2 = 0; j2 < 32; j2++) {
            float vj = rsv[j2]; int gj = cgid[j2];
            if (vj > vv || (vj == vv && gj < gg)) rank++;
        }
        if (rank < k) {
            g_topidx[b * 32 + rank] = gg;
            out_idx_f[(size_t)b * k + rank] = (float)gg;
        }
    }
}

// ---------------- fused warm pipeline: balanced mu/lv per warp (R15 win) ----
__global__ __launch_bounds__(512)
void k_warm(const float* __restrict__ feats,
            const float* __restrict__ b_mu, const float* __restrict__ b_lv,
            const float* __restrict__ b_dec, float* __restrict__ newf) {
    extern __shared__ char smem[];
    const int M = g_nwarm;
    const int m0 = blockIdx.x * 128;
    if (m0 >= M) return;

    const int tid = threadIdx.x, wid = tid >> 5, lane = tid & 31;
    const int wm = wid >> 2, wn = wid & 3;
    const uint32_t sb = smem_u32(smem);

    float acc[2][8][4];
    #pragma unroll
    for (int mi = 0; mi < 2; mi++)
        #pragma unroll
        for (int ni = 0; ni < 8; ni++)
            #pragma unroll
            for (int j = 0; j < 4; j++) acc[mi][ni][j] = 0.f;

    const int aRow = (lane & 15), aColSel = (lane >> 4) << 3;
    const int bRow = (lane & 7) + ((lane & 16) >> 1), bColSel = lane & 8;
    const int gq = lane >> 2, qq = (lane & 3) * 2;

    int arows[4];
    #pragma unroll
    for (int it = 0; it < 4; it++) {
        int r = m0 + ((tid + it * 512) >> 4);
        arows[it] = g_warm_idx[(r < M) ? r : m0];
    }

    // ===== phase 1: [mu|lv] balanced =====
    for (int c = 0; c < 4; c++) {
        const int k0 = c * 64;
        #pragma unroll
        for (int it = 0; it < 4; it++) {
            int id = tid + it * 512;
            float4 v = *(const float4*)(feats + (size_t)arows[it] * 256 + k0 + (id & 15) * 4);
            split_store4(smem, id >> 4, (id & 15) * 4, v, OFF_AH, OFF_AL);
        }
        #pragma unroll
        for (int it = 0; it < 4; it++) {
            int id = tid + it * 512;
            int n = id >> 3, q = id & 7;
            size_t src = (size_t)n * 256 + k0 + q * 8;
            size_t dst = ((size_t)n * TSTRIDE + q * 8) * 2;
            *(uint4*)(smem + OFF_BH + dst) = *(const uint4*)(g_Wh + src);
            *(uint4*)(smem + OFF_BL + dst) = *(const uint4*)(g_Wl + src);
        }
        __syncthreads();

        #pragma unroll
        for (int kk = 0; kk < 64; kk += 16) {
            uint32_t ah[2][4], al[2][4];
            #pragma unroll
            for (int mi = 0; mi < 2; mi++) {
                uint32_t off = ((uint32_t)(wm * 32 + mi * 16 + aRow) * TSTRIDE + kk + aColSel) * 2;
                ldm4(sb + OFF_AH + off, ah[mi]);
                ldm4(sb + OFF_AL + off, al[mi]);
            }
            #pragma unroll
            for (int np = 0; np < 4; np++) {
                const bool mu_np = (np < 2);
                int n0 = mu_np ? (wn * 32 + np * 16) : (128 + wn * 32 + (np - 2) * 16);
                uint32_t boff = ((uint32_t)(n0 + bRow) * TSTRIDE + kk + bColSel) * 2;
                uint32_t bh[4], bl[4];
                ldm4(sb + OFF_BH + boff, bh);
                if (mu_np) ldm4(sb + OFF_BL + boff, bl);
                #pragma unroll
                for (int mi = 0; mi < 2; mi++) {
                    MMA16816(acc[mi][np * 2],     ah[mi], &bh[0]);
                    MMA16816(acc[mi][np * 2 + 1], ah[mi], &bh[2]);
                    if (mu_np) {
                        MMA16816(acc[mi][np * 2],     al[mi], &bh[0]);
                        MMA16816(acc[mi][np * 2],     ah[mi], &bl[0]);
                        MMA16816(acc[mi][np * 2 + 1], al[mi], &bh[2]);
                        MMA16816(acc[mi][np * 2 + 1], ah[mi], &bl[2]);
                    }
                }
            }
        }
        __syncthreads();
    }

    // ===== epilogue 1: ni<4 = mu cols (wn*32+..), ni>=4 = lv cols ==========
    float kl = 0.f;
    #pragma unroll
    for (int mi = 0; mi < 2; mi++) {
        #pragma unroll
        for (int half = 0; half < 2; half++) {
            int rl = wm * 32 + mi * 16 + gq + half * 8;
            int grow = m0 + rl;
            bool valid = grow < M;
            #pragma unroll
            for (int ni = 0; ni < 8; ni++) {
                const bool is_lv = (ni >= 4);
                int cl = wn * 32 + (is_lv ? (ni - 4) : ni) * 8 + qq;
                float bias0 = is_lv ? b_lv[cl] : b_mu[cl];
                float bias1 = is_lv ? b_lv[cl + 1] : b_mu[cl + 1];
                float v0 = acc[mi][ni][half * 2 + 0] + bias0;
                float v1 = acc[mi][ni][half * 2 + 1] + bias1;
                if (!is_lv) {
                    __nv_bfloat16 h0 = __float2bfloat16(v0), h1 = __float2bfloat16(v1);
                    float l0 = v0 - __bfloat162float(h0), l1 = v1 - __bfloat162float(h1);
                    uint32_t o = ((uint32_t)rl * MUSTRIDE + cl) * 2;
                    *(uint32_t*)(smem + OFF_MUH + o) = pk2(h0, h1);
                    *(uint32_t*)(smem + OFF_MUL + o) = pk2(__float2bfloat16(l0), __float2bfloat16(l1));
                    if (valid) kl += 0.5f * (v0 * v0 + v1 * v1) - 1.0f;
                } else if (valid) {
                    kl += 0.5f * (expf(v0) + expf(v1)) - 0.5f * (v0 + v1);
                }
            }
        }
    }
    #pragma unroll
    for (int o = 16; o > 0; o >>= 1) kl += __shfl_xor_sync(0xffffffffu, kl, o);
    if (lane == 0 && kl != 0.f) atomicAdd(&g_kl_sum, (double)kl);
    __syncthreads();

    // ===== phase 2: dec = mu @ Wdec^T =====
    #pragma unroll
    for (int mi = 0; mi < 2; mi++)
        #pragma unroll
        for (int ni = 0; ni < 8; ni++)
            #pragma unroll
            for (int j = 0; j < 4; j++) acc[mi][ni][j] = 0.f;

    for (int c = 0; c < 2; c++) {
        const int k0 = c * 64;
        #pragma unroll
        for (int it = 0; it < 4; it++) {
            int id = tid + it * 512;
            int n = id >> 3, q = id & 7;
            size_t src = (size_t)n * 128 + k0 + q * 8;
            size_t dst = ((size_t)n * TSTRIDE + q * 8) * 2;
            *(uint4*)(smem + OFF_BH + dst) = *(const uint4*)(g_Dh + src);
            *(uint4*)(smem + OFF_BL + dst) = *(const uint4*)(g_Dl + src);
        }
        __syncthreads();

        #pragma unroll
        for (int kk = 0; kk < 64; kk += 16) {
            uint32_t ah[2][4], al[2][4];
            #pragma unroll
            for (int mi = 0; mi < 2; mi++) {
                uint32_t off = ((uint32_t)(wm * 32 + mi * 16 + aRow) * MUSTRIDE + k0 + kk + aColSel) * 2;
                ldm4(sb + OFF_MUH + off, ah[mi]);
                ldm4(sb + OFF_MUL + off, al[mi]);
            }
            #pragma unroll
            for (int np = 0; np < 4; np++) {
                int n0 = wn * 64 + np * 16;
                uint32_t boff = ((uint32_t)(n0 + bRow) * TSTRIDE + kk + bColSel) * 2;
                uint32_t bh[4], bl[4];
                ldm4(sb + OFF_BH + boff, bh);
                ldm4(sb + OFF_BL + boff, bl);
                #pragma unroll
                for (int mi = 0; mi < 2; mi++) {
                    MMA16816(acc[mi][np * 2],     ah[mi], &bh[0]);
                    MMA16816(acc[mi][np * 2],     al[mi], &bh[0]);
                    MMA16816(acc[mi][np * 2],     ah[mi], &bl[0]);
                    MMA16816(acc[mi][np * 2 + 1], ah[mi], &bh[2]);
                    MMA16816(acc[mi][np * 2 + 1], al[mi], &bh[2]);
                    MMA16816(acc[mi][np * 2 + 1], ah[mi], &bl[2]);
                }
            }
        }
        __syncthreads();
    }

    #pragma unroll
    for (int mi = 0; mi < 2; mi++) {
        #pragma unroll
        for (int half = 0; half < 2; half++) {
            int grow = m0 + wm * 32 + mi * 16 + gq + half * 8;
            if (grow >= M) continue;
            int wr = g_warm_idx[grow];
            #pragma unroll
            for (int ni = 0; ni < 8; ni++) {
                int col = wn * 64 + ni * 8 + qq;
                float2 v = make_float2(acc[mi][ni][half * 2 + 0] + b_dec[col],
                                       acc[mi][ni][half * 2 + 1] + b_dec[col + 1]);
                *(float2*)(newf + (size_t)wr * 256 + col) = v;
            }
        }
    }
}

// ---------------- gather + kl finalize ----------------
__global__ __launch_bounds__(256) void k_gather(const float* __restrict__ newf,
                                                float* __restrict__ ret, int D, int k,
                                                float* __restrict__ klp, int W) {
    int r = blockIdx.x;
    if (r == 0 && threadIdx.x == 0) {
        int n = g_nwarm > 0 ? g_nwarm : 1;
        *klp = (float)(g_kl_sum / ((double)n * (double)W));
    }
    int row = g_topidx[(r / k) * 32 + (r % k)];
    const float* s = newf + (size_t)row * D;
    float* d = ret + (size_t)r * D;
    for (int c = threadIdx.x; c < D; c += blockDim.x) d[c] = s[c];
}

extern "C" void kernel_launch(void* const* d_in, const int* in_sizes, int n_in,
                              void* d_out, int out_size) {
    const float* feats = (const float*)d_in[0];
    const int*   tiers = (const int*)d_in[1];
    const float* query = (const float*)d_in[2];
    const float* W_mu  = (const float*)d_in[3];
    const float* b_mu  = (const float*)d_in[4];
    const float* W_lv  = (const float*)d_in[5];
    const float* b_lv  = (const float*)d_in[6];
    const float* W_dec = (const float*)d_in[7];
    const float* b_dec = (const float*)d_in[8];

    const int N = in_sizes[1];
    const int D = in_sizes[0] / N;
    const int B = in_sizes[2] / D;
    const int W = in_sizes[4];
    const long k = ((long)out_size - (long)N * D - 1) / ((long)B * (D + 1));

    float* out   = (float*)d_out;
    float* newf  = out;
    float* klp   = out + (size_t)N * D;
    float* ret   = klp + 1;
    float* tidxf = ret + (size_t)B * k * D;

    cudaFuncSetAttribute(k_warm, cudaFuncAttributeMaxDynamicSharedMemorySize, DSMEM_SZ);

    const int gy = (N + 127) / 128;
    long n4 = (long)N * D / 4;

    // order: k_warm is the 4th launch -> profiled by ncu (-s 5 -c 1)
    k_initq<<<B, 256>>>(query, D);
    k_partition<<<(N + 255) / 256, 256>>>(tiers, N);
    k_wprep<<<384, 256>>>(W_mu, W_lv, W_dec);
    k_warm<<<gy, 512, DSMEM_SZ>>>(feats, b_mu, b_lv, b_dec, newf);

    k_copy4<<<(unsigned)((n4 + 255) / 256), 256>>>((const float4*)feats, (float4*)newf, tiers, n4);
    k_sim<<<gy, 256>>>(feats, N);
    k_topk1<<<dim3(8, B), 256>>>(N);
    k_topk2<<<B, 256>>>(feats, (int)k, tidxf);
    k_gather<<<B * (int)k, 256>>>(newf, ret, D, (int)k, klp, W);
}

// round 17
// speedup vs baseline: 1.2077x; 1.0103x over previous
#include <cuda_runtime.h>
#include <cuda_bf16.h>
#include <math.h>
#include <stdint.h>

// ---------------- static scratch (no allocations allowed) ----------------
#define MAXN 204800
#define MAXB 64

__device__ int    g_warm_idx[MAXN];
__device__ int    g_cold_idx[MAXN];
__device__ int    g_nwarm;
__device__ int    g_ncold;
__device__ double g_kl_sum;
__device__ float  g_sim[(size_t)MAXB * MAXN];
__device__ float  g_qn[MAXB * 256];
__device__ __nv_bfloat16 g_qnb[MAXB * 256];
__device__ float  g_rown[MAXN];
__device__ int    g_topidx[MAXB * 32];
__device__ float  g_cand_v[MAXB * 256];
__device__ int    g_cand_g[MAXB * 256];
__device__ __nv_bfloat16 g_muh[(size_t)MAXN * 128];  // mu hi, warm-compacted
__device__ __nv_bfloat16 g_mul[(size_t)MAXN * 128];  // mu lo
__device__ __nv_bfloat16 g_Wh[256 * 256];
__device__ __nv_bfloat16 g_Wl[256 * 256];
__device__ __nv_bfloat16 g_Dh[256 * 128];
__device__ __nv_bfloat16 g_Dl[256 * 128];

// ---------------- helpers ----------------
__device__ __forceinline__ uint32_t pk2(__nv_bfloat16 a, __nv_bfloat16 b) {
    return (uint32_t)__bfloat16_as_ushort(a) | ((uint32_t)__bfloat16_as_ushort(b) << 16);
}
__device__ __forceinline__ uint32_t smem_u32(const void* p) {
    uint32_t a;
    asm("{ .reg .u64 t; cvta.to.shared.u64 t, %1; cvt.u32.u64 %0, t; }" : "=r"(a) : "l"(p));
    return a;
}

#define MMA16816(c, a, b) asm volatile( \
    "mma.sync.aligned.m16n8k16.row.col.f32.bf16.bf16.f32 " \
    "{%0,%1,%2,%3}, {%4,%5,%6,%7}, {%8,%9}, {%0,%1,%2,%3};" \
    : "+f"((c)[0]), "+f"((c)[1]), "+f"((c)[2]), "+f"((c)[3]) \
    : "r"((a)[0]), "r"((a)[1]), "r"((a)[2]), "r"((a)[3]), "r"((b)[0]), "r"((b)[1]))

__device__ __forceinline__ void ldm4(uint32_t addr, uint32_t r[4]) {
    asm volatile("ldmatrix.sync.aligned.m8n8.x4.shared.b16 {%0,%1,%2,%3}, [%4];"
                 : "=r"(r[0]), "=r"(r[1]), "=r"(r[2]), "=r"(r[3]) : "r"(addr));
}

#define TSTRIDE 72
// 2-CTA kernels: A tiles 64x72 bf16 (9216B each), B tiles 256x72 (36864B each)
#define OFF2_AH 0
#define OFF2_AL 9216
#define OFF2_BH 18432
#define OFF2_BL 55296
#define DSMEM2  92160

__device__ __forceinline__ void split_store4(char* smem, int m, int k, float4 v,
                                             int off_hi, int off_lo) {
    __nv_bfloat16 h0 = __float2bfloat16(v.x), h1 = __float2bfloat16(v.y);
    __nv_bfloat16 h2 = __float2bfloat16(v.z), h3 = __float2bfloat16(v.w);
    float l0 = v.x - __bfloat162float(h0), l1 = v.y - __bfloat162float(h1);
    float l2 = v.z - __bfloat162float(h2), l3 = v.w - __bfloat162float(h3);
    size_t base = (size_t)m * TSTRIDE + k;
    *(uint2*)(smem + off_hi + base * 2) = make_uint2(pk2(h0, h1), pk2(h2, h3));
    *(uint2*)(smem + off_lo + base * 2) =
        make_uint2(pk2(__float2bfloat16(l0), __float2bfloat16(l1)),
                   pk2(__float2bfloat16(l2), __float2bfloat16(l3)));
}

// ---------------- init + query norm ----------------
__global__ __launch_bounds__(256) void k_initq(const float* __restrict__ q, int D) {
    int b = blockIdx.x, t = threadIdx.x;
    if (b == 0 && t == 0) { g_nwarm = 0; g_ncold = 0; g_kl_sum = 0.0; }
    float ss = 0.f;
    for (int c = t; c < D; c += 256) { float v = q[(size_t)b * D + c]; ss += v * v; }
    __shared__ float red[256];
    red[t] = ss; __syncthreads();
    for (int s = 128; s > 0; s >>= 1) { if (t < s) red[t] += red[t + s]; __syncthreads(); }
    float scale = 1.f / (sqrtf(red[0]) + 1e-10f);
    for (int c = t; c < D; c += 256) {
        float v = q[(size_t)b * D + c] * scale;
        g_qn[(size_t)b * D + c] = v;
        g_qnb[(size_t)b * D + c] = __float2bfloat16(v);
    }
}

// ---------------- warp-aggregated tier partition ----------------
__global__ void k_partition(const int* __restrict__ tiers, int N) {
    int i = blockIdx.x * blockDim.x + threadIdx.x;
    bool in = i < N;
    int t = in ? tiers[i] : 0;
    unsigned m1 = __ballot_sync(0xffffffffu, t == 1);
    unsigned m2 = __ballot_sync(0xffffffffu, t == 2);
    int lane = threadIdx.x & 31;
    unsigned lt = (1u << lane) - 1u;
    if (t == 1) {
        int ldr = __ffs(m1) - 1;
        int base = 0;
        if (lane == ldr) base = atomicAdd(&g_nwarm, __popc(m1));
        base = __shfl_sync(m1, base, ldr);
        g_warm_idx[base + __popc(m1 & lt)] = i;
    } else if (t == 2) {
        int ldr = __ffs(m2) - 1;
        int base = 0;
        if (lane == ldr) base = atomicAdd(&g_ncold, __popc(m2));
        base = __shfl_sync(m2, base, ldr);
        g_cold_idx[base + __popc(m2 & lt)] = i;
    }
}

// ---------------- copy (skip warm) + fused per-row |x|^2 -------------------
__global__ __launch_bounds__(256) void k_copy4(const float4* __restrict__ src,
                                               float4* __restrict__ dst,
                                               const int* __restrict__ tiers, long n4) {
    long i = (long)blockIdx.x * blockDim.x + threadIdx.x;
    int t = threadIdx.x;
    float4 v = make_float4(0.f, 0.f, 0.f, 0.f);
    if (i < n4) {
        v = src[i];
        int row = (int)(i >> 6);
        if (tiers[row] != 1) dst[i] = v;
    }
    float ss = v.x * v.x + v.y * v.y + v.z * v.z + v.w * v.w;
    #pragma unroll
    for (int o = 16; o > 0; o >>= 1) ss += __shfl_xor_sync(0xffffffffu, ss, o);
    __shared__ float wred[8];
    if ((t & 31) == 0) wred[t >> 5] = ss;
    __syncthreads();
    if (t < 4) {
        long r0 = ((long)blockIdx.x * 256) >> 6;
        if (r0 + t < (n4 >> 6)) g_rown[r0 + t] = wred[2 * t] + wred[2 * t + 1];
    }
}

// ---------------- weight pre-convert ----------------
__global__ __launch_bounds__(256) void k_wprep(const float* __restrict__ W_mu,
                                               const float* __restrict__ W_lv,
                                               const float* __restrict__ W_dec) {
    int idx = blockIdx.x * blockDim.x + threadIdx.x;
    if (idx < 65536) {
        int n = idx >> 8, k = idx & 255;
        float w = (n < 128) ? W_mu[(size_t)n * 256 + k] : W_lv[(size_t)(n - 128) * 256 + k];
        __nv_bfloat16 h = __float2bfloat16(w);
        g_Wh[idx] = h;
        g_Wl[idx] = __float2bfloat16(w - __bfloat162float(h));
    } else if (idx < 65536 + 32768) {
        int j = idx - 65536;
        float w = W_dec[j];
        __nv_bfloat16 h = __float2bfloat16(w);
        g_Dh[j] = h;
        g_Dl[j] = __float2bfloat16(w - __bfloat162float(h));
    }
}

// ---------------- VAE encoder: 2 CTAs/SM, M-tile 64 ------------------------
// [mu|lv](64x256) = X_warm(64x256) @ [Wmu;Wlv]^T. Per warp: 32 mu cols
// (3-pass hi/lo) + 32 lv cols (1-pass). Epilogue: KL + mu -> gmem split bf16.
__global__ __launch_bounds__(256, 2)
void k_vae2(const float* __restrict__ feats,
            const float* __restrict__ b_mu, const float* __restrict__ b_lv) {
    extern __shared__ char smem[];
    const int M = g_nwarm;
    const int m0 = blockIdx.x * 64;
    if (m0 >= M) return;

    const int tid = threadIdx.x, wid = tid >> 5, lane = tid & 31;
    const int wm = wid >> 2, wn = wid & 3;   // 2x4 warps, warp tile 32r x (32mu+32lv)
    const uint32_t sb = smem_u32(smem);

    float acc[2][8][4];
    #pragma unroll
    for (int mi = 0; mi < 2; mi++)
        #pragma unroll
        for (int ni = 0; ni < 8; ni++)
            #pragma unroll
            for (int j = 0; j < 4; j++) acc[mi][ni][j] = 0.f;

    const int aRow = (lane & 15), aColSel = (lane >> 4) << 3;
    const int bRow = (lane & 7) + ((lane & 16) >> 1), bColSel = lane & 8;
    const int gq = lane >> 2, qq = (lane & 3) * 2;

    int arows[4];
    #pragma unroll
    for (int it = 0; it < 4; it++) {
        int r = m0 + ((tid + it * 256) >> 4);
        arows[it] = g_warm_idx[(r < M) ? r : m0];
    }

    for (int c = 0; c < 4; c++) {
        const int k0 = c * 64;
        // A: 64 rows x 64 cols fp32 -> split bf16 (1024 float4)
        #pragma unroll
        for (int it = 0; it < 4; it++) {
            int id = tid + it * 256;
            float4 v = *(const float4*)(feats + (size_t)arows[it] * 256 + k0 + (id & 15) * 4);
            split_store4(smem, id >> 4, (id & 15) * 4, v, OFF2_AH, OFF2_AL);
        }
        // B: 256 rows x 64 cols hi+lo (2048 uint4 each)
        #pragma unroll
        for (int it = 0; it < 8; it++) {
            int id = tid + it * 256;
            int n = id >> 3, q = id & 7;
            size_t src = (size_t)n * 256 + k0 + q * 8;
            size_t dst = ((size_t)n * TSTRIDE + q * 8) * 2;
            *(uint4*)(smem + OFF2_BH + dst) = *(const uint4*)(g_Wh + src);
            *(uint4*)(smem + OFF2_BL + dst) = *(const uint4*)(g_Wl + src);
        }
        __syncthreads();

        #pragma unroll
        for (int kk = 0; kk < 64; kk += 16) {
            uint32_t ah[2][4], al[2][4];
            #pragma unroll
            for (int mi = 0; mi < 2; mi++) {
                uint32_t off = ((uint32_t)(wm * 32 + mi * 16 + aRow) * TSTRIDE + kk + aColSel) * 2;
                ldm4(sb + OFF2_AH + off, ah[mi]);
                ldm4(sb + OFF2_AL + off, al[mi]);
            }
            #pragma unroll
            for (int np = 0; np < 4; np++) {
                const bool mu_np = (np < 2);
                int n0 = mu_np ? (wn * 32 + np * 16) : (128 + wn * 32 + (np - 2) * 16);
                uint32_t boff = ((uint32_t)(n0 + bRow) * TSTRIDE + kk + bColSel) * 2;
                uint32_t bh[4], bl[4];
                ldm4(sb + OFF2_BH + boff, bh);
                if (mu_np) ldm4(sb + OFF2_BL + boff, bl);
                #pragma unroll
                for (int mi = 0; mi < 2; mi++) {
                    MMA16816(acc[mi][np * 2],     ah[mi], &bh[0]);
                    MMA16816(acc[mi][np * 2 + 1], ah[mi], &bh[2]);
                    if (mu_np) {
                        MMA16816(acc[mi][np * 2],     al[mi], &bh[0]);
                        MMA16816(acc[mi][np * 2],     ah[mi], &bl[0]);
                        MMA16816(acc[mi][np * 2 + 1], al[mi], &bh[2]);
                        MMA16816(acc[mi][np * 2 + 1], ah[mi], &bl[2]);
                    }
                }
            }
        }
        __syncthreads();
    }

    // epilogue: KL + mu -> gmem split bf16
    float kl = 0.f;
    #pragma unroll
    for (int mi = 0; mi < 2; mi++) {
        #pragma unroll
        for (int half = 0; half < 2; half++) {
            int grow = m0 + wm * 32 + mi * 16 + gq + half * 8;
            bool valid = grow < M;
            #pragma unroll
            for (int ni = 0; ni < 8; ni++) {
                const bool is_lv = (ni >= 4);
                int cl = wn * 32 + (is_lv ? (ni - 4) : ni) * 8 + qq;
                float bias0 = is_lv ? b_lv[cl] : b_mu[cl];
                float bias1 = is_lv ? b_lv[cl + 1] : b_mu[cl + 1];
                float v0 = acc[mi][ni][half * 2 + 0] + bias0;
                float v1 = acc[mi][ni][half * 2 + 1] + bias1;
                if (!is_lv) {
                    if (valid) {
                        __nv_bfloat16 h0 = __float2bfloat16(v0), h1 = __float2bfloat16(v1);
                        float l0 = v0 - __bfloat162float(h0), l1 = v1 - __bfloat162float(h1);
                        size_t o = (size_t)grow * 128 + cl;
                        *(uint32_t*)(g_muh + o) = pk2(h0, h1);
                        *(uint32_t*)(g_mul + o) = pk2(__float2bfloat16(l0), __float2bfloat16(l1));
                        kl += 0.5f * (v0 * v0 + v1 * v1) - 1.0f;
                    }
                } else if (valid) {
                    kl += 0.5f * (expf(v0) + expf(v1)) - 0.5f * (v0 + v1);
                }
            }
        }
    }
    #pragma unroll
    for (int o = 16; o > 0; o >>= 1) kl += __shfl_xor_sync(0xffffffffu, kl, o);
    if (lane == 0 && kl != 0.f) atomicAdd(&g_kl_sum, (double)kl);
}

// ---------------- decoder: 2 CTAs/SM, M-tile 64 ----------------------------
// dec(64x256) = mu(64x128) @ Wdec^T, 3-pass; scatter rows to new_features.
__global__ __launch_bounds__(256, 2)
void k_dec2(const float* __restrict__ b_dec, float* __restrict__ newf) {
    extern __shared__ char smem[];
    const int M = g_nwarm;
    const int m0 = blockIdx.x * 64;
    if (m0 >= M) return;

    const int tid = threadIdx.x, wid = tid >> 5, lane = tid & 31;
    const int wm = wid >> 2, wn = wid & 3;   // warp tile 32 rows x 64 cols
    const uint32_t sb = smem_u32(smem);

    float acc[2][8][4];
    #pragma unroll
    for (int mi = 0; mi < 2; mi++)
        #pragma unroll
        for (int ni = 0; ni < 8; ni++)
            #pragma unroll
            for (int j = 0; j < 4; j++) acc[mi][ni][j] = 0.f;

    const int aRow = (lane & 15), aColSel = (lane >> 4) << 3;
    const int bRow = (lane & 7) + ((lane & 16) >> 1), bColSel = lane & 8;
    const int gq = lane >> 2, qq = (lane & 3) * 2;

    for (int c = 0; c < 2; c++) {
        const int k0 = c * 64;
        // A: mu hi/lo 64 rows x 64 cols (512 uint4 each)
        #pragma unroll
        for (int it = 0; it < 2; it++) {
            int id = tid + it * 256;
            int m = id >> 3, q = id & 7;
            int r = m0 + m;
            size_t src = (size_t)((r < M) ? r : m0) * 128 + k0 + q * 8;
            size_t dst = ((size_t)m * TSTRIDE + q * 8) * 2;
            *(uint4*)(smem + OFF2_AH + dst) = *(const uint4*)(g_muh + src);
            *(uint4*)(smem + OFF2_AL + dst) = *(const uint4*)(g_mul + src);
        }
        // B: Wdec 256 rows x 64 cols hi+lo
        #pragma unroll
        for (int it = 0; it < 8; it++) {
            int id = tid + it * 256;
            int n = id >> 3, q = id & 7;
            size_t src = (size_t)n * 128 + k0 + q * 8;
            size_t dst = ((size_t)n * TSTRIDE + q * 8) * 2;
            *(uint4*)(smem + OFF2_BH + dst) = *(const uint4*)(g_Dh + src);
            *(uint4*)(smem + OFF2_BL + dst) = *(const uint4*)(g_Dl + src);
        }
        __syncthreads();

        #pragma unroll
        for (int kk = 0; kk < 64; kk += 16) {
            uint32_t ah[2][4], al[2][4];
            #pragma unroll
            for (int mi = 0; mi < 2; mi++) {
                uint32_t off = ((uint32_t)(wm * 32 + mi * 16 + aRow) * TSTRIDE + kk + aColSel) * 2;
                ldm4(sb + OFF2_AH + off, ah[mi]);
                ldm4(sb + OFF2_AL + off, al[mi]);
            }
            #pragma unroll
            for (int np = 0; np < 4; np++) {
                int n0 = wn * 64 + np * 16;
                uint32_t boff = ((uint32_t)(n0 + bRow) * TSTRIDE + kk + bColSel) * 2;
                uint32_t bh[4], bl[4];
                ldm4(sb + OFF2_BH + boff, bh);
                ldm4(sb + OFF2_BL + boff, bl);
                #pragma unroll
                for (int mi = 0; mi < 2; mi++) {
                    MMA16816(acc[mi][np * 2],     ah[mi], &bh[0]);
                    MMA16816(acc[mi][np * 2],     al[mi], &bh[0]);
                    MMA16816(acc[mi][np * 2],     ah[mi], &bl[0]);
                    MMA16816(acc[mi][np * 2 + 1], ah[mi], &bh[2]);
                    MMA16816(acc[mi][np * 2 + 1], al[mi], &bh[2]);
                    MMA16816(acc[mi][np * 2 + 1], ah[mi], &bl[2]);
                }
            }
        }
        __syncthreads();
    }

    #pragma unroll
    for (int mi = 0; mi < 2; mi++) {
        #pragma unroll
        for (int half = 0; half < 2; half++) {
            int grow = m0 + wm * 32 + mi * 16 + gq + half * 8;
            if (grow >= M) continue;
            int wr = g_warm_idx[grow];
            #pragma unroll
            for (int ni = 0; ni < 8; ni++) {
                int col = wn * 64 + ni * 8 + qq;
                float2 v = make_float2(acc[mi][ni][half * 2 + 0] + b_dec[col],
                                       acc[mi][ni][half * 2 + 1] + b_dec[col + 1]);
                *(float2*)(newf + (size_t)wr * 256 + col) = v;
            }
        }
    }
}

// ---------------- approx sim: single-pass bf16 HMMA ------------------------
__global__ __launch_bounds__(256)
void k_sim(const float* __restrict__ feats, int simld) {
    __shared__ char smem[128 * TSTRIDE * 2 + 64 * TSTRIDE * 2];
    const int OFF_B = 128 * TSTRIDE * 2;
    const int M = g_ncold;
    const int m0 = blockIdx.x * 128;
    if (m0 >= M) return;

    const int tid = threadIdx.x, wid = tid >> 5, lane = tid & 31;
    const int wm = wid >> 1, wn = wid & 1;
    const uint32_t sb = smem_u32(smem);

    float acc[2][4][4];
    #pragma unroll
    for (int mi = 0; mi < 2; mi++)
        #pragma unroll
        for (int ni = 0; ni < 4; ni++)
            #pragma unroll
            for (int j = 0; j < 4; j++) acc[mi][ni][j] = 0.f;

    const int aRow = (lane & 15), aColSel = (lane >> 4) << 3;
    const int bRow = (lane & 7) + ((lane & 16) >> 1), bColSel = lane & 8;
    const int gq = lane >> 2, qq = (lane & 3) * 2;

    int arows[8];
    #pragma unroll
    for (int it = 0; it < 8; it++) {
        int r = m0 + ((tid + it * 256) >> 4);
        arows[it] = g_cold_idx[(r < M) ? r : m0];
    }

    for (int c = 0; c < 4; c++) {
        const int k0 = c * 64;
        #pragma unroll
        for (int it = 0; it < 8; it++) {
            int id = tid + it * 256;
            int m = id >> 4, kq = id & 15;
            float4 v = *(const float4*)(feats + (size_t)arows[it] * 256 + k0 + kq * 4);
            *(uint2*)(smem + ((size_t)m * TSTRIDE + kq * 4) * 2) =
                make_uint2(pk2(__float2bfloat16(v.x), __float2bfloat16(v.y)),
                           pk2(__float2bfloat16(v.z), __float2bfloat16(v.w)));
        }
        #pragma unroll
        for (int it = 0; it < 2; it++) {
            int id = tid + it * 256;
            int n = id >> 3, u = id & 7;
            *(uint4*)(smem + OFF_B + ((size_t)n * TSTRIDE + u * 8) * 2) =
                *(const uint4*)(g_qnb + (size_t)n * 256 + k0 + u * 8);
        }
        __syncthreads();

        #pragma unroll
        for (int kk = 0; kk < 64; kk += 16) {
            uint32_t a[2][4];
            #pragma unroll
            for (int mi = 0; mi < 2; mi++) {
                uint32_t off = ((uint32_t)(wm * 32 + mi * 16 + aRow) * TSTRIDE + kk + aColSel) * 2;
                ldm4(sb + off, a[mi]);
            }
            #pragma unroll
            for (int np = 0; np < 2; np++) {
                uint32_t boff = ((uint32_t)(wn * 32 + np * 16 + bRow) * TSTRIDE + kk + bColSel) * 2;
                uint32_t bfr[4];
                ldm4(sb + OFF_B + boff, bfr);
                #pragma unroll
                for (int mi = 0; mi < 2; mi++) {
                    MMA16816(acc[mi][np * 2],     a[mi], &bfr[0]);
                    MMA16816(acc[mi][np * 2 + 1], a[mi], &bfr[2]);
                }
            }
        }
        __syncthreads();
    }

    #pragma unroll
    for (int mi = 0; mi < 2; mi++) {
        #pragma unroll
        for (int half = 0; half < 2; half++) {
            int rl = wm * 32 + mi * 16 + gq + half * 8;
            int j = m0 + rl;
            if (j >= M) continue;
            int grown = g_cold_idx[j];
            float inv = 1.f / (sqrtf(g_rown[grown]) + 1e-10f);
            #pragma unroll
            for (int ni = 0; ni < 4; ni++) {
                int q = wn * 32 + ni * 8 + qq;
                g_sim[(size_t)q * simld + j] = acc[mi][ni][half * 2 + 0] * inv;
                g_sim[(size_t)(q + 1) * simld + j] = acc[mi][ni][half * 2 + 1] * inv;
            }
        }
    }
}

// ---------------- top-k stage 1: per-slice top-32 --------------------------
__global__ __launch_bounds__(256) void k_topk1(int simld) {
    const int sl = blockIdx.x, b = blockIdx.y;
    const int ncold = g_ncold;
    const int t = threadIdx.x, lane = t & 31, warp = t >> 5;
    const int s0 = (int)(((long)ncold * sl) >> 3);
    const int s1 = (int)(((long)ncold * (sl + 1)) >> 3);

    float tv[4]; int tg[4];
    #pragma unroll
    for (int s = 0; s < 4; s++) { tv[s] = -INFINITY; tg[s] = 0x7fffffff; }

    const float* srow = g_sim + (size_t)b * simld;
    int j = s0 + t;
    for (; j + 768 < s1; j += 1024) {
        float v0 = srow[j], v1 = srow[j + 256], v2 = srow[j + 512], v3 = srow[j + 768];
        #pragma unroll
        for (int u = 0; u < 4; u++) {
            float v = (u == 0) ? v0 : (u == 1) ? v1 : (u == 2) ? v2 : v3;
            int jj = j + u * 256;
            if (v > tv[3]) {
                tv[3] = v; tg[3] = g_cold_idx[jj];
                #pragma unroll
                for (int s = 2; s >= 0; s--)
                    if (tv[s + 1] > tv[s]) {
                        float x = tv[s]; tv[s] = tv[s + 1]; tv[s + 1] = x;
                        int y = tg[s]; tg[s] = tg[s + 1]; tg[s + 1] = y;
                    }
            }
        }
    }
    for (; j < s1; j += 256) {
        float v = srow[j];
        if (v > tv[3]) {
            tv[3] = v; tg[3] = g_cold_idx[j];
            #pragma unroll
            for (int s = 2; s >= 0; s--)
                if (tv[s + 1] > tv[s]) {
                    float x = tv[s]; tv[s] = tv[s + 1]; tv[s + 1] = x;
                    int y = tg[s]; tg[s] = tg[s + 1]; tg[s + 1] = y;
                }
        }
    }

    __shared__ float wv[8];
    __shared__ int   wg[8];
    __shared__ int   wing_s;

    float* outv = g_cand_v + ((size_t)b * 8 + sl) * 32;
    int*   outg = g_cand_g + ((size_t)b * 8 + sl) * 32;

    for (int sel = 0; sel < 32; sel++) {
        float v = tv[0]; int g = tg[0];
        #pragma unroll
        for (int o = 16; o > 0; o >>= 1) {
            float ov = __shfl_xor_sync(0xffffffffu, v, o);
            int   og = __shfl_xor_sync(0xffffffffu, g, o);
            if (ov > v || (ov == v && og < g)) { v = ov; g = og; }
        }
        if (lane == 0) { wv[warp] = v; wg[warp] = g; }
        __syncthreads();
        if (t == 0) {
            float bv = wv[0]; int bg = wg[0];
            #pragma unroll
            for (int u = 1; u < 8; u++)
                if (wv[u] > bv || (wv[u] == bv && wg[u] < bg)) { bv = wv[u]; bg = wg[u]; }
            wing_s = bg;
            outv[sel] = bv; outg[sel] = bg;
        }
        __syncthreads();
        if (tg[0] == wing_s) {
            tv[0] = tv[1]; tg[0] = tg[1];
            tv[1] = tv[2]; tg[1] = tg[2];
            tv[2] = tv[3]; tg[2] = tg[3];
            tv[3] = -INFINITY; tg[3] = 0x7fffffff;
        }
        __syncthreads();
    }
}

// ---------------- top-k stage 2: merge + exact fp32 rescore ----------------
__global__ __launch_bounds__(256) void k_topk2(const float* __restrict__ feats,
                                               int k, float* __restrict__ out_idx_f) {
    const int b = blockIdx.x;
    const int t = threadIdx.x, lane = t & 31, warp = t >> 5;

    float v = g_cand_v[(size_t)b * 256 + t];
    int   g = g_cand_g[(size_t)b * 256 + t];

    __shared__ float wv[8];
    __shared__ int   wg[8];
    __shared__ int   wing_s;
    __shared__ int   cgid[32];
    __shared__ float rsv[32];

    for (int sel = 0; sel < 32; sel++) {
        float mv = v; int mg = g;
        #pragma unroll
        for (int o = 16; o > 0; o >>= 1) {
            float ov = __shfl_xor_sync(0xffffffffu, mv, o);
            int   og = __shfl_xor_sync(0xffffffffu, mg, o);
            if (ov > mv || (ov == mv && og < mg)) { mv = ov; mg = og; }
        }
        if (lane == 0) { wv[warp] = mv; wg[warp] = mg; }
        __syncthreads();
        if (t == 0) {
            float bv = wv[0]; int bg = wg[0];
            #pragma unroll
            for (int u = 1; u < 8; u++)
                if (wv[u] > bv || (wv[u] == bv && wg[u] < bg)) { bv = wv[u]; bg = wg[u]; }
            wing_s = bg;
            cgid[sel] = bg;
        }
        __syncthreads();
        if (g == wing_s) { v = -INFINITY; g = 0x7fffffff; }
        __syncthreads();
    }

    {
        int c = t >> 3, e = t & 7;
        int gg = cgid[c];
        float part = 0.f;
        if (gg != 0x7fffffff) {
            const float* fr = feats + (size_t)gg * 256 + e * 32;
            const float* qr = g_qn + (size_t)b * 256 + e * 32;
            #pragma unroll
            for (int x = 0; x < 32; x += 4) {
                float4 f = *(const float4*)(fr + x);
                float4 qv = *(const float4*)(qr + x);
                part += f.x * qv.x + f.y * qv.y + f.z * qv.z + f.w * qv.w;
            }
        }
        #pragma unroll
        for (int o = 4; o > 0; o >>= 1) part += __shfl_xor_sync(0xffffffffu, part, o);
        if (e == 0)
            rsv[c] = (gg != 0x7fffffff) ? part / (sqrtf(g_rown[gg]) + 1e-10f) : -INFINITY;
    }
    __syncthreads();

    if (t < 32) {
        float vv = rsv[t]; int gg = cgid[t];
        int rank = 0;
        #pragma unroll
        for (int j2 = 0; j2 < 32; j2++) {
            float vj = rsv[j2]; int gj = cgid[j2];
            if (vj > vv || (vj == vv && gj < gg)) rank++;
        }
        if (rank < k) {
            g_topidx[b * 32 + rank] = gg;
            out_idx_f[(size_t)b * k + rank] = (float)gg;
        }
    }
}

// ---------------- gather + kl finalize ----------------
__global__ __launch_bounds__(256) void k_gather(const float* __restrict__ newf,
                                                float* __restrict__ ret, int D, int k,
                                                float* __restrict__ klp, int W) {
    int r = blockIdx.x;
    if (r == 0 && threadIdx.x == 0) {
        int n = g_nwarm > 0 ? g_nwarm : 1;
        *klp = (float)(g_kl_sum / ((double)n * (double)W));
    }
    int row = g_topidx[(r / k) * 32 + (r % k)];
    const float* s = newf + (size_t)row * D;
    float* d = ret + (size_t)r * D;
    for (int c = threadIdx.x; c < D; c += blockDim.x) d[c] = s[c];
}

extern "C" void kernel_launch(void* const* d_in, const int* in_sizes, int n_in,
                              void* d_out, int out_size) {
    const float* feats = (const float*)d_in[0];
    const int*   tiers = (const int*)d_in[1];
    const float* query = (const float*)d_in[2];
    const float* W_mu  = (const float*)d_in[3];
    const float* b_mu  = (const float*)d_in[4];
    const float* W_lv  = (const float*)d_in[5];
    const float* b_lv  = (const float*)d_in[6];
    const float* W_dec = (const float*)d_in[7];
    const float* b_dec = (const float*)d_in[8];

    const int N = in_sizes[1];
    const int D = in_sizes[0] / N;
    const int B = in_sizes[2] / D;
    const int W = in_sizes[4];
    const long k = ((long)out_size - (long)N * D - 1) / ((long)B * (D + 1));

    float* out   = (float*)d_out;
    float* newf  = out;
    float* klp   = out + (size_t)N * D;
    float* ret   = klp + 1;
    float* tidxf = ret + (size_t)B * k * D;

    cudaFuncSetAttribute(k_vae2, cudaFuncAttributeMaxDynamicSharedMemorySize, DSMEM2);
    cudaFuncSetAttribute(k_dec2, cudaFuncAttributeMaxDynamicSharedMemorySize, DSMEM2);

    const int gy = (N + 127) / 128;
    const int gyv = (N + 63) / 64;
    long n4 = (long)N * D / 4;

    // order: k_vae2 is the 4th launch -> profiled by ncu (-s 5 -c 1)
    k_initq<<<B, 256>>>(query, D);
    k_partition<<<(N + 255) / 256, 256>>>(tiers, N);
    k_wprep<<<384, 256>>>(W_mu, W_lv, W_dec);
    k_vae2<<<gyv, 256, DSMEM2>>>(feats, b_mu, b_lv);
    k_dec2<<<gyv, 256, DSMEM2>>>(b_dec, newf);

    k_copy4<<<(unsigned)((n4 + 255) / 256), 256>>>((const float4*)feats, (float4*)newf, tiers, n4);
    k_sim<<<gy, 256>>>(feats, N);
    k_topk1<<<dim3(8, B), 256>>>(N);
    k_topk2<<<B, 256>>>(feats, (int)k, tidxf);
    k_gather<<<B * (int)k, 256>>>(newf, ret, D, (int)k, klp, W);
}